// round 16
// baseline (speedup 1.0000x reference)
#include <cuda_runtime.h>
#include <cuda_fp16.h>

#define N_NODES 50000
#define N_EDGES 800000
#define CH 128
#define OUT_CH 64
#define SCAN_B 1024
#define SCAN_NB ((N_NODES + SCAN_B - 1) / SCAN_B)   // 49
#define PAD_A 36
#define PAD_B 136
#define GEMM_SMEM ((128 * PAD_B + 128 * PAD_A) * 4)

// ---- persistent device scratch (no allocation allowed) ----
__device__ int   g_is64;
__device__ int   g_deg[N_NODES];
__device__ float g_dinv[N_NODES];
__device__ int   g_rowptr[N_NODES + 1];
__device__ int   g_fill[N_NODES];
__device__ int   g_bsum[64];
__device__ int   g_scan_ctr;
__device__ int   g_csr[N_EDGES];
__device__ __align__(16) __half g_h1h[(size_t)N_NODES * CH];
__device__ __align__(16) __half g_hidh[(size_t)N_NODES * CH];
__device__ __align__(16) __half g_h23h[(size_t)N_NODES * CH];
__device__ __align__(16) float  g_wc[CH * CH];

__device__ __forceinline__ int edge_at(const void* p, int i) {
    if (g_is64) return (int)(((const long long*)p)[i]);
    return ((const int*)p)[i];
}

// ---------------------------------------------------------------------------
__global__ void k_pre(const void* ei, const float* __restrict__ W2,
                      const float* __restrict__ W3) {
    int i = blockIdx.x * blockDim.x + threadIdx.x;
    if (i < N_NODES) g_deg[i] = 1;
    if (i < CH * CH) {
        int k = i >> 7, c = i & 127;
        g_wc[i] = (c < OUT_CH) ? W2[k * OUT_CH + c] : W3[k * OUT_CH + (c - OUT_CH)];
    }
    if (i == 1) g_scan_ctr = 0;
    if (i == 0) {
        const long long* p = (const long long*)ei;
        int ok64 = 1;
        for (int t = 0; t < 256; t++) {
            long long v = p[t];
            if (v < 0 || v >= N_NODES) { ok64 = 0; break; }
        }
        g_is64 = ok64;
    }
}

__global__ void k_deg(const void* __restrict__ ei) {
    int e = blockIdx.x * blockDim.x + threadIdx.x;
    if (e < N_EDGES) {
        int c = edge_at(ei, N_EDGES + e);
        if ((unsigned)c < N_NODES) atomicAdd(&g_deg[c], 1);
    }
}

// fused scan + grid-sync; also seeds g_fill with rowptr
__global__ void k_scan() {
    __shared__ int wsum[32];
    __shared__ int s_part[2];
    __shared__ int s_off;
    int t = threadIdx.x;
    int i = blockIdx.x * SCAN_B + t;
    int lane = t & 31, wid = t >> 5;
    int v = 0;
    if (i < N_NODES) {
        int d = g_deg[i];
        v = d - 1;
        g_dinv[i] = rsqrtf((float)d);
    }
    int x = v;
    #pragma unroll
    for (int d = 1; d < 32; d <<= 1) {
        int y = __shfl_up_sync(0xffffffffu, x, d);
        if (lane >= d) x += y;
    }
    if (lane == 31) wsum[wid] = x;
    __syncthreads();
    if (wid == 0) {
        int y = wsum[lane];
        #pragma unroll
        for (int d = 1; d < 32; d <<= 1) {
            int z = __shfl_up_sync(0xffffffffu, y, d);
            if (lane >= d) y += z;
        }
        wsum[lane] = y;
    }
    __syncthreads();
    int base = (wid > 0) ? wsum[wid - 1] : 0;
    int local = base + x - v;
    if (t == 0) {
        g_bsum[blockIdx.x] = wsum[31];
        __threadfence();
        atomicAdd(&g_scan_ctr, 1);
        while (atomicAdd(&g_scan_ctr, 0) < SCAN_NB) { }
    }
    __syncthreads();
    if (t < 64) {
        int w = (t < blockIdx.x) ? g_bsum[t] : 0;
        #pragma unroll
        for (int d = 16; d; d >>= 1) w += __shfl_down_sync(0xffffffffu, w, d);
        if ((t & 31) == 0) s_part[t >> 5] = w;
    }
    __syncthreads();
    if (t == 0) s_off = s_part[0] + s_part[1];
    __syncthreads();
    if (i < N_NODES) {
        int rp = local + s_off;
        g_rowptr[i] = rp;
        g_fill[i] = rp;
    }
    if (i == 0) g_rowptr[N_NODES] = N_EDGES;
}

__global__ void k_fill(const void* __restrict__ ei) {
    int e = blockIdx.x * blockDim.x + threadIdx.x;
    if (e < N_EDGES) {
        int s = edge_at(ei, e);
        int c = edge_at(ei, N_EDGES + e);
        if ((unsigned)c < N_NODES && (unsigned)s < N_NODES) {
            int pos = atomicAdd(&g_fill[c], 1);
            if ((unsigned)pos < N_EDGES) g_csr[pos] = s;
        }
    }
}

// ---------------------------------------------------------------------------
// tf32 tensor-core GEMM: C_half[M,128] = A[M,128] @ B[128,128]
__device__ __forceinline__ unsigned f2tf32(float f) {
    unsigned u;
    asm("cvt.rna.tf32.f32 %0, %1;" : "=r"(u) : "f"(f));
    return u;
}

__device__ __forceinline__ void mma_tf32(float& c0, float& c1, float& c2, float& c3,
                                         unsigned a0, unsigned a1, unsigned a2, unsigned a3,
                                         unsigned b0, unsigned b1) {
    asm volatile(
        "mma.sync.aligned.m16n8k8.row.col.f32.tf32.tf32.f32 "
        "{%0,%1,%2,%3}, {%4,%5,%6,%7}, {%8,%9}, {%0,%1,%2,%3};"
        : "+f"(c0), "+f"(c1), "+f"(c2), "+f"(c3)
        : "r"(a0), "r"(a1), "r"(a2), "r"(a3), "r"(b0), "r"(b1));
}

template <bool A_HALF>
__device__ __forceinline__ void gemm_tf32_body(const void* __restrict__ Av,
                                               const float* __restrict__ B,
                                               __half* __restrict__ C, int M) {
    extern __shared__ unsigned smem_u[];
    unsigned* Bs = smem_u;                    // [128][PAD_B]
    unsigned* As = smem_u + 128 * PAD_B;      // [128][PAD_A]
    int tid = threadIdx.x;                    // 256
    int lane = tid & 31, wid = tid >> 5;
    int g = lane >> 2, t4 = lane & 3;
    int wm = wid >> 1, wn = wid & 1;
    int m_base = wm * 32, n_base = wn * 64;
    int m0 = blockIdx.x * 128;

    for (int idx = tid; idx < 128 * 32; idx += 256) {
        int k = idx >> 5, nq = (idx & 31) << 2;
        float4 v = *(const float4*)(B + (size_t)k * 128 + nq);
        unsigned* d = &Bs[k * PAD_B + nq];
        d[0] = f2tf32(v.x); d[1] = f2tf32(v.y);
        d[2] = f2tf32(v.z); d[3] = f2tf32(v.w);
    }

    float acc[2][8][4];
    #pragma unroll
    for (int mi = 0; mi < 2; mi++)
        #pragma unroll
        for (int ni = 0; ni < 8; ni++)
            #pragma unroll
            for (int q = 0; q < 4; q++) acc[mi][ni][q] = 0.f;

    for (int kc = 0; kc < 4; kc++) {
        int k0c = kc * 32;
        __syncthreads();
        for (int idx = tid; idx < 128 * 8; idx += 256) {
            int m = idx >> 3, kq = (idx & 7) << 2;
            float4 v = make_float4(0.f, 0.f, 0.f, 0.f);
            if (m0 + m < M) {
                if (A_HALF) {
                    const __half2* p = (const __half2*)((const __half*)Av +
                                        (size_t)(m0 + m) * 128 + k0c + kq);
                    float2 f01 = __half22float2(p[0]);
                    float2 f23 = __half22float2(p[1]);
                    v = make_float4(f01.x, f01.y, f23.x, f23.y);
                } else {
                    v = *(const float4*)((const float*)Av + (size_t)(m0 + m) * 128 + k0c + kq);
                }
            }
            unsigned* d = &As[m * PAD_A + kq];
            d[0] = f2tf32(v.x); d[1] = f2tf32(v.y);
            d[2] = f2tf32(v.z); d[3] = f2tf32(v.w);
        }
        __syncthreads();
        #pragma unroll
        for (int kk = 0; kk < 4; kk++) {
            int k0 = kk * 8;
            unsigned a[2][4];
            #pragma unroll
            for (int mi = 0; mi < 2; mi++) {
                int r0 = m_base + mi * 16 + g;
                a[mi][0] = As[r0 * PAD_A + k0 + t4];
                a[mi][1] = As[(r0 + 8) * PAD_A + k0 + t4];
                a[mi][2] = As[r0 * PAD_A + k0 + t4 + 4];
                a[mi][3] = As[(r0 + 8) * PAD_A + k0 + t4 + 4];
            }
            unsigned b[8][2];
            int K0 = k0c + k0;
            #pragma unroll
            for (int ni = 0; ni < 8; ni++) {
                int cbase = n_base + ni * 8 + g;
                b[ni][0] = Bs[(K0 + t4) * PAD_B + cbase];
                b[ni][1] = Bs[(K0 + t4 + 4) * PAD_B + cbase];
            }
            #pragma unroll
            for (int mi = 0; mi < 2; mi++)
                #pragma unroll
                for (int ni = 0; ni < 8; ni++)
                    mma_tf32(acc[mi][ni][0], acc[mi][ni][1], acc[mi][ni][2], acc[mi][ni][3],
                             a[mi][0], a[mi][1], a[mi][2], a[mi][3],
                             b[ni][0], b[ni][1]);
        }
    }

    #pragma unroll
    for (int mi = 0; mi < 2; mi++) {
        int r0 = m0 + m_base + mi * 16 + g;
        int r1 = r0 + 8;
        #pragma unroll
        for (int ni = 0; ni < 8; ni++) {
            int col = n_base + ni * 8 + 2 * t4;
            if (r0 < M)
                *(__half2*)(C + (size_t)r0 * 128 + col) =
                    __floats2half2_rn(acc[mi][ni][0], acc[mi][ni][1]);
            if (r1 < M)
                *(__half2*)(C + (size_t)r1 * 128 + col) =
                    __floats2half2_rn(acc[mi][ni][2], acc[mi][ni][3]);
        }
    }
}

__global__ void k_gemm1(const float* __restrict__ A, const float* __restrict__ B) {
    gemm_tf32_body<false>(A, B, g_h1h, N_NODES);
}
__global__ void k_gemm2() {
    gemm_tf32_body<true>(g_hidh, g_wc, g_h23h, N_NODES);
}

// ---------------------------------------------------------------------------
// 2-nodes-per-warp gather: 16 lanes per node, LDG.128 row strips (16B/lane).
// acc8 = fp32 accumulation of this lane's 8 channels.
__device__ __forceinline__ void gather_acc8(const __half* __restrict__ h, int node,
                                            int sub, float* acc) {
    int start = __ldg(&g_rowptr[node]);
    int end   = __ldg(&g_rowptr[node + 1]);
    int len = end - start;
    int olen = __shfl_xor_sync(0xffffffffu, len, 16);
    int maxlen = (len > olen) ? len : olen;
    float a[8], b[8];
    #pragma unroll
    for (int q = 0; q < 8; q++) { a[q] = 0.f; b[q] = 0.f; }
    int j = 0;
    for (; j + 1 < maxlen; j += 2) {
        bool v0 = (j < len), v1 = (j + 1 < len);
        int s0 = v0 ? __ldg(&g_csr[start + j]) : 0;
        int s1 = v1 ? __ldg(&g_csr[start + j + 1]) : 0;
        float w0 = v0 ? __ldg(&g_dinv[s0]) : 0.f;
        float w1 = v1 ? __ldg(&g_dinv[s1]) : 0.f;
        uint4 r0 = __ldg((const uint4*)(h + (size_t)s0 * CH) + sub);
        uint4 r1 = __ldg((const uint4*)(h + (size_t)s1 * CH) + sub);
        float2 u0 = __half22float2(*(__half2*)&r0.x);
        float2 u1 = __half22float2(*(__half2*)&r0.y);
        float2 u2 = __half22float2(*(__half2*)&r0.z);
        float2 u3 = __half22float2(*(__half2*)&r0.w);
        float2 q0 = __half22float2(*(__half2*)&r1.x);
        float2 q1 = __half22float2(*(__half2*)&r1.y);
        float2 q2 = __half22float2(*(__half2*)&r1.z);
        float2 q3 = __half22float2(*(__half2*)&r1.w);
        a[0] = fmaf(w0, u0.x, a[0]); b[0] = fmaf(w1, q0.x, b[0]);
        a[1] = fmaf(w0, u0.y, a[1]); b[1] = fmaf(w1, q0.y, b[1]);
        a[2] = fmaf(w0, u1.x, a[2]); b[2] = fmaf(w1, q1.x, b[2]);
        a[3] = fmaf(w0, u1.y, a[3]); b[3] = fmaf(w1, q1.y, b[3]);
        a[4] = fmaf(w0, u2.x, a[4]); b[4] = fmaf(w1, q2.x, b[4]);
        a[5] = fmaf(w0, u2.y, a[5]); b[5] = fmaf(w1, q2.y, b[5]);
        a[6] = fmaf(w0, u3.x, a[6]); b[6] = fmaf(w1, q3.x, b[6]);
        a[7] = fmaf(w0, u3.y, a[7]); b[7] = fmaf(w1, q3.y, b[7]);
    }
    if (j < maxlen) {
        bool v0 = (j < len);
        int s0 = v0 ? __ldg(&g_csr[start + j]) : 0;
        float w0 = v0 ? __ldg(&g_dinv[s0]) : 0.f;
        uint4 r0 = __ldg((const uint4*)(h + (size_t)s0 * CH) + sub);
        float2 u0 = __half22float2(*(__half2*)&r0.x);
        float2 u1 = __half22float2(*(__half2*)&r0.y);
        float2 u2 = __half22float2(*(__half2*)&r0.z);
        float2 u3 = __half22float2(*(__half2*)&r0.w);
        a[0] = fmaf(w0, u0.x, a[0]); a[1] = fmaf(w0, u0.y, a[1]);
        a[2] = fmaf(w0, u1.x, a[2]); a[3] = fmaf(w0, u1.y, a[3]);
        a[4] = fmaf(w0, u2.x, a[4]); a[5] = fmaf(w0, u2.y, a[5]);
        a[6] = fmaf(w0, u3.x, a[6]); a[7] = fmaf(w0, u3.y, a[7]);
    }
    #pragma unroll
    for (int q = 0; q < 8; q++) acc[q] = a[q] + b[q];
}

__global__ void k_gather1(const float* __restrict__ b1) {
    int gtid = blockIdx.x * blockDim.x + threadIdx.x;
    int lane = gtid & 31;
    int sub = lane & 15;
    int node = (gtid >> 5) * 2 + (lane >> 4);
    if (node >= N_NODES) return;
    float acc[8];
    gather_acc8(g_h1h, node, sub, acc);
    float me = __ldg(&g_dinv[node]);
    float m2 = me * me;
    uint4 sr = __ldg((const uint4*)(g_h1h + (size_t)node * CH) + sub);
    float2 s0 = __half22float2(*(__half2*)&sr.x);
    float2 s1 = __half22float2(*(__half2*)&sr.y);
    float2 s2 = __half22float2(*(__half2*)&sr.z);
    float2 s3 = __half22float2(*(__half2*)&sr.w);
    float sf[8] = {s0.x, s0.y, s1.x, s1.y, s2.x, s2.y, s3.x, s3.y};
    int c0 = sub * 8;
    float4 bb0 = *(const float4*)(b1 + c0);
    float4 bb1 = *(const float4*)(b1 + c0 + 4);
    float bbf[8] = {bb0.x, bb0.y, bb0.z, bb0.w, bb1.x, bb1.y, bb1.z, bb1.w};
    float o[8];
    #pragma unroll
    for (int q = 0; q < 8; q++)
        o[q] = fmaxf(fmaf(acc[q], me, fmaf(sf[q], m2, bbf[q])), 0.f);
    uint4 pk;
    *(__half2*)&pk.x = __floats2half2_rn(o[0], o[1]);
    *(__half2*)&pk.y = __floats2half2_rn(o[2], o[3]);
    *(__half2*)&pk.z = __floats2half2_rn(o[4], o[5]);
    *(__half2*)&pk.w = __floats2half2_rn(o[6], o[7]);
    *((uint4*)(g_hidh + (size_t)node * CH) + sub) = pk;
}

__global__ void k_gather2(const float* __restrict__ b2, const float* __restrict__ b3,
                          float* __restrict__ out) {
    int gtid = blockIdx.x * blockDim.x + threadIdx.x;
    int lane = gtid & 31;
    int sub = lane & 15;
    int node = (gtid >> 5) * 2 + (lane >> 4);
    if (node >= N_NODES) return;
    float acc[8];
    gather_acc8(g_h23h, node, sub, acc);
    float me = __ldg(&g_dinv[node]);
    float m2 = me * me;
    uint4 sr = __ldg((const uint4*)(g_h23h + (size_t)node * CH) + sub);
    float2 s0 = __half22float2(*(__half2*)&sr.x);
    float2 s1 = __half22float2(*(__half2*)&sr.y);
    float2 s2 = __half22float2(*(__half2*)&sr.z);
    float2 s3 = __half22float2(*(__half2*)&sr.w);
    float sf[8] = {s0.x, s0.y, s1.x, s1.y, s2.x, s2.y, s3.x, s3.y};
    int c0 = sub * 8;
    const float* bias = (sub < 8) ? (b2 + c0) : (b3 + (c0 - 64));
    float4 bb0 = *(const float4*)bias;
    float4 bb1 = *(const float4*)(bias + 4);
    float bbf[8] = {bb0.x, bb0.y, bb0.z, bb0.w, bb1.x, bb1.y, bb1.z, bb1.w};
    float o[8];
    #pragma unroll
    for (int q = 0; q < 8; q++)
        o[q] = fmaxf(fmaf(acc[q], me, fmaf(sf[q], m2, bbf[q])), 0.f);
    float* dst = (sub < 8)
        ? (out + (size_t)node * OUT_CH + c0)
        : (out + (size_t)N_NODES * OUT_CH + (size_t)node * OUT_CH + (c0 - 64));
    *(float4*)dst       = make_float4(o[0], o[1], o[2], o[3]);
    *(float4*)(dst + 4) = make_float4(o[4], o[5], o[6], o[7]);
}

// ---------------------------------------------------------------------------
extern "C" void kernel_launch(void* const* d_in, const int* in_sizes, int n_in,
                              void* d_out, int out_size) {
    const float* x  = (const float*)d_in[0];
    const void*  ei = d_in[1];
    const float* W1 = (const float*)d_in[2];
    const float* b1 = (const float*)d_in[3];
    const float* W2 = (const float*)d_in[4];
    const float* b2 = (const float*)d_in[5];
    const float* W3 = (const float*)d_in[6];
    const float* b3 = (const float*)d_in[7];
    float* out = (float*)d_out;

    cudaFuncSetAttribute(k_gemm1, cudaFuncAttributeMaxDynamicSharedMemorySize, GEMM_SMEM);
    cudaFuncSetAttribute(k_gemm2, cudaFuncAttributeMaxDynamicSharedMemorySize, GEMM_SMEM);

    k_pre<<<(N_NODES + 255) / 256, 256>>>(ei, W2, W3);
    k_deg<<<(N_EDGES + 255) / 256, 256>>>(ei);
    k_scan<<<SCAN_NB, SCAN_B>>>();
    k_fill<<<(N_EDGES + 255) / 256, 256>>>(ei);

    k_gemm1<<<(N_NODES + 127) / 128, 256, GEMM_SMEM>>>(x, W1);
    k_gather1<<<(N_NODES / 2 * 32 + 255) / 256, 256>>>(b1);

    k_gemm2<<<(N_NODES + 127) / 128, 256, GEMM_SMEM>>>();
    k_gather2<<<(N_NODES / 2 * 32 + 255) / 256, 256>>>(b2, b3, out);
}